// round 1
// baseline (speedup 1.0000x reference)
#include <cuda_runtime.h>

#define N_NODES 100000
#define N_EDGES 3200000
#define ED 128          // embed dim
#define NG 128          // num graphs
#define NC 10           // num classes
#define KM 32           // m-chunk staged in shared per GEMM iteration

// Scratch (no allocations allowed; device globals are the sanctioned path)
__device__ float g_s[N_NODES];                    // s[n] = feat[n] + sum_in feat[src]
__device__ float g_c[(size_t)N_NODES * NG];       // w[m,g] weight/count matrix (51.2 MB)
__device__ float g_hg[NG * ED];                   // per-graph summed h2pre
__device__ int   g_cnt[NG];                       // nodes per graph

// ---------------------------------------------------------------------------
// K0: zero the 51.2MB count matrix (float4 stores)
__global__ void k_zero_c() {
    size_t i = (size_t)blockIdx.x * blockDim.x + threadIdx.x;
    if (i < (size_t)N_NODES * NG / 4)
        ((float4*)g_c)[i] = make_float4(0.f, 0.f, 0.f, 0.f);
}

// K0b: init s = feat, zero hg accumulator and counts
__global__ void k_init(const float* __restrict__ feat) {
    int i = blockIdx.x * blockDim.x + threadIdx.x;
    if (i < N_NODES) g_s[i] = feat[i];
    if (i < NG * ED) g_hg[i] = 0.f;
    if (i < NG)      g_cnt[i] = 0;
}

// ---------------------------------------------------------------------------
// K1: per-edge scalar pass.
//   s[dst] += feat[src]                       (conv1 scalar aggregation)
//   c[src, graph(dst)] += 1                   (edge-count weight for pooled conv2)
__global__ void k_edges(const int4* __restrict__ src4, const int4* __restrict__ dst4,
                        const float* __restrict__ feat, const int* __restrict__ gids) {
    int i = blockIdx.x * blockDim.x + threadIdx.x;
    if (i >= N_EDGES / 4) return;
    int4 s4 = src4[i];
    int4 t4 = dst4[i];
#define EDGE_OP(s, t) {                                        \
        float fv = __ldg(&feat[(s)]);                          \
        atomicAdd(&g_s[(t)], fv);                              \
        int g = __ldg(&gids[(t)]);                             \
        atomicAdd(&g_c[(size_t)(s) * NG + g], 1.0f);           \
    }
    EDGE_OP(s4.x, t4.x);
    EDGE_OP(s4.y, t4.y);
    EDGE_OP(s4.z, t4.z);
    EDGE_OP(s4.w, t4.w);
#undef EDGE_OP
}

// ---------------------------------------------------------------------------
// K2: per-node pass: add self-term indicator c[n, graph(n)] += 1; count nodes/graph
__global__ void k_nodes(const int* __restrict__ gids) {
    __shared__ int hist[NG];
    int tid = threadIdx.x;
    if (tid < NG) hist[tid] = 0;
    __syncthreads();
    int i = blockIdx.x * blockDim.x + tid;
    if (i < N_NODES) {
        int g = gids[i];
        atomicAdd(&g_c[(size_t)i * NG + g], 1.0f);
        atomicAdd(&hist[g], 1);
    }
    __syncthreads();
    if (tid < NG && hist[tid]) atomicAdd(&g_cnt[tid], hist[tid]);
}

// ---------------------------------------------------------------------------
// K3: hg_sum[g,d] = sum_m c[m,g] * relu(s[m]*W1[d] + b1[d])
// Outer-product GEMM: 256 threads as 16x16, each owns an interleaved 8x8 tile.
__global__ __launch_bounds__(256) void k_gemm(const float* __restrict__ W1,
                                              const float* __restrict__ b1) {
    __shared__ float c_sh[KM][NG];   // 16 KB
    __shared__ float f_sh[KM][ED];   // 16 KB
    __shared__ float w_sh[ED], bb_sh[ED];

    int tid = threadIdx.x;
    int tx = tid & 15;        // -> d = tx + 16*j
    int ty = tid >> 4;        // -> g = ty + 16*i
    if (tid < ED) { w_sh[tid] = W1[tid]; bb_sh[tid] = b1[tid]; }

    float acc[8][8];
#pragma unroll
    for (int i = 0; i < 8; i++)
#pragma unroll
        for (int j = 0; j < 8; j++) acc[i][j] = 0.f;

    int nblk = gridDim.x;
    int per = (N_NODES + nblk - 1) / nblk;
    int m_begin = blockIdx.x * per;
    int m_end = m_begin + per;
    if (m_end > N_NODES) m_end = N_NODES;
    __syncthreads();

    for (int m0 = m_begin; m0 < m_end; m0 += KM) {
        int mcnt = m_end - m0;
        if (mcnt > KM) mcnt = KM;
        // stage c rows (coalesced float4)
        for (int idx = tid; idx < mcnt * (NG / 4); idx += 256) {
            int r = idx >> 5;           // NG/4 = 32
            int col4 = idx & 31;
            float4 v = *(const float4*)&g_c[(size_t)(m0 + r) * NG + col4 * 4];
            *(float4*)&c_sh[r][col4 * 4] = v;
        }
        // stage F rows: relu(s*w + b)
        for (int idx = tid; idx < mcnt * ED; idx += 256) {
            int r = idx >> 7;
            int d = idx & 127;
            float sv = g_s[m0 + r];
            f_sh[r][d] = fmaxf(fmaf(sv, w_sh[d], bb_sh[d]), 0.0f);
        }
        __syncthreads();
        for (int mm = 0; mm < mcnt; mm++) {
            float cv[8], fv[8];
#pragma unroll
            for (int i = 0; i < 8; i++) cv[i] = c_sh[mm][ty + 16 * i];
#pragma unroll
            for (int j = 0; j < 8; j++) fv[j] = f_sh[mm][tx + 16 * j];
#pragma unroll
            for (int i = 0; i < 8; i++)
#pragma unroll
                for (int j = 0; j < 8; j++)
                    acc[i][j] = fmaf(cv[i], fv[j], acc[i][j]);
        }
        __syncthreads();
    }
    // flush partials
#pragma unroll
    for (int i = 0; i < 8; i++)
#pragma unroll
        for (int j = 0; j < 8; j++)
            atomicAdd(&g_hg[(ty + 16 * i) * ED + (tx + 16 * j)], acc[i][j]);
}

// ---------------------------------------------------------------------------
// K4: head. Per graph g (one block, 128 threads):
//   hg = hg_sum / count; m1 = hg@W2+b2; m2 = relu(m1@Wf1+bf1); out = m2@Wf2+bf2
__global__ __launch_bounds__(128) void k_head(const float* __restrict__ W2,
                                              const float* __restrict__ b2,
                                              const float* __restrict__ Wf1,
                                              const float* __restrict__ bf1,
                                              const float* __restrict__ Wf2,
                                              const float* __restrict__ bf2,
                                              float* __restrict__ out) {
    __shared__ float a_sh[ED];
    __shared__ float h_sh[ED];
    int g = blockIdx.x;
    int d = threadIdx.x;

    float invc = 1.0f / fmaxf((float)g_cnt[g], 1.0f);
    a_sh[d] = g_hg[g * ED + d] * invc;
    __syncthreads();

    // m1 = hg @ W2 + b2
    float acc = b2[d];
#pragma unroll 8
    for (int k = 0; k < ED; k++) acc = fmaf(a_sh[k], W2[k * ED + d], acc);
    h_sh[d] = acc;
    __syncthreads();

    // m2 = relu(m1 @ Wf1 + bf1)
    acc = bf1[d];
#pragma unroll 8
    for (int k = 0; k < ED; k++) acc = fmaf(h_sh[k], Wf1[k * ED + d], acc);
    acc = fmaxf(acc, 0.0f);
    __syncthreads();          // everyone done reading a_sh from stage 1? (stage1 read a_sh; safe after first sync chain)
    a_sh[d] = acc;
    __syncthreads();

    // out = m2 @ Wf2 + bf2
    if (d < NC) {
        float o = bf2[d];
#pragma unroll 8
        for (int k = 0; k < ED; k++) o = fmaf(a_sh[k], Wf2[k * NC + d], o);
        out[g * NC + d] = o;
    }
}

// ---------------------------------------------------------------------------
extern "C" void kernel_launch(void* const* d_in, const int* in_sizes, int n_in,
                              void* d_out, int out_size) {
    const float* feat = (const float*)d_in[0];
    const int*   src  = (const int*)d_in[1];
    const int*   dst  = (const int*)d_in[2];
    const int*   gids = (const int*)d_in[3];
    const float* W1   = (const float*)d_in[4];
    const float* b1   = (const float*)d_in[5];
    const float* W2   = (const float*)d_in[6];
    const float* b2   = (const float*)d_in[7];
    const float* Wf1  = (const float*)d_in[8];
    const float* bf1  = (const float*)d_in[9];
    const float* Wf2  = (const float*)d_in[10];
    const float* bf2  = (const float*)d_in[11];
    float* out = (float*)d_out;

    k_zero_c<<<(N_NODES * NG / 4 + 255) / 256, 256>>>();
    k_init<<<(N_NODES + 255) / 256, 256>>>(feat);
    k_edges<<<(N_EDGES / 4 + 255) / 256, 256>>>((const int4*)src, (const int4*)dst, feat, gids);
    k_nodes<<<(N_NODES + 255) / 256, 256>>>(gids);
    k_gemm<<<296, 256>>>(W1, b1);
    k_head<<<NG, ED>>>(W2, b2, Wf1, bf1, Wf2, bf2, out);
}

// round 2
// speedup vs baseline: 1.1511x; 1.1511x over previous
#include <cuda_runtime.h>
#include <math_constants.h>

#define N_NODES 100000
#define N_EDGES 3200000
#define ED 128          // embed dim
#define NG 128          // num graphs
#define NC 10           // num classes
#define NB 129          // buckets = thresholds + 1

// Scratch (device globals — no allocations allowed)
__device__ float  g_s[N_NODES];              // s[n] = feat[n] + sum_in feat[src]
__device__ float2 g_sb[N_NODES];             // packed (s, bucket)
__device__ float  g_hist[NG * NB * 2];       // per (graph,bucket): {sum_s, count} — 132KB
__device__ int    g_cnt[NG];                 // nodes per graph
__device__ float  g_T[ED];                   // sorted thresholds
__device__ int    g_rank[ED];                // sorted position of threshold d
__device__ int    g_side[ED];                // 1: active = s > t_d (suffix); 0: active = s < t_d

// ---------------------------------------------------------------------------
// K0: init s=feat, zero hist + cnt
__global__ void k_init(const float* __restrict__ feat) {
    int i = blockIdx.x * blockDim.x + threadIdx.x;
    if (i < N_NODES) g_s[i] = feat[i];
    if (i < NG * NB * 2) g_hist[i] = 0.f;
    if (i < NG) g_cnt[i] = 0;
}

// K1: thresholds + rank (1 block, 128 threads)
__global__ void k_prep(const float* __restrict__ W1, const float* __restrict__ b1) {
    __shared__ float ts[ED];
    int d = threadIdx.x;
    float w = W1[d], b = b1[d];
    float t;
    int side;
    if (w > 0.f)      { t = -b / w; side = 1; }
    else if (w < 0.f) { t = -b / w; side = 0; }
    else              { side = 1; t = (b > 0.f) ? -CUDART_INF_F : CUDART_INF_F; }
    ts[d] = t;
    __syncthreads();
    int r = 0;
#pragma unroll 8
    for (int j = 0; j < ED; j++) {
        float tj = ts[j];
        r += (tj < t) || (tj == t && j < d);
    }
    g_rank[d] = r;
    g_side[d] = side;
    g_T[r] = t;
}

// ---------------------------------------------------------------------------
// K2: edge pass 1 — s[dst] += feat[src]
__global__ void k_edges1(const int4* __restrict__ src4, const int4* __restrict__ dst4,
                         const float* __restrict__ feat) {
    int i = blockIdx.x * blockDim.x + threadIdx.x;
    if (i >= N_EDGES / 4) return;
    int4 s4 = src4[i];
    int4 t4 = dst4[i];
    atomicAdd(&g_s[t4.x], __ldg(&feat[s4.x]));
    atomicAdd(&g_s[t4.y], __ldg(&feat[s4.y]));
    atomicAdd(&g_s[t4.z], __ldg(&feat[s4.z]));
    atomicAdd(&g_s[t4.w], __ldg(&feat[s4.w]));
}

// ---------------------------------------------------------------------------
// K3: per node — bucket via binary search; self term into hist; count per graph
__global__ __launch_bounds__(256) void k_bucket(const int* __restrict__ gids) {
    __shared__ float T[ED];
    __shared__ int hcnt[NG];
    int tid = threadIdx.x;
    if (tid < ED) T[tid] = g_T[tid];
    if (tid < NG) hcnt[tid] = 0;
    __syncthreads();
    int n = blockIdx.x * 256 + tid;
    if (n < N_NODES) {
        float s = g_s[n];
        // b = #{ j : T[j] <= s }  in [0, 128]
        int b = 0;
#pragma unroll
        for (int st = 128; st > 0; st >>= 1) {
            int nb = b + st;
            if (nb <= ED && T[nb - 1] <= s) b = nb;
        }
        int g = gids[n];
        g_sb[n] = make_float2(s, __int_as_float(b));
        int base = (g * NB + b) * 2;
        atomicAdd(&g_hist[base], s);
        atomicAdd(&g_hist[base + 1], 1.0f);
        atomicAdd(&hcnt[g], 1);
    }
    __syncthreads();
    if (tid < NG && hcnt[tid]) atomicAdd(&g_cnt[tid], hcnt[tid]);
}

// ---------------------------------------------------------------------------
// K4: edge pass 2 — hist[graph(dst)][bucket(src)] += (s[src], 1)
__global__ void k_edges2(const int4* __restrict__ src4, const int4* __restrict__ dst4,
                         const int* __restrict__ gids) {
    int i = blockIdx.x * blockDim.x + threadIdx.x;
    if (i >= N_EDGES / 4) return;
    int4 s4 = src4[i];
    int4 t4 = dst4[i];
#define EOP(s, t) {                                            \
        float2 sb = __ldg(&g_sb[(s)]);                         \
        int g = __ldg(&gids[(t)]);                             \
        int base = (g * NB + __float_as_int(sb.y)) * 2;        \
        atomicAdd(&g_hist[base], sb.x);                        \
        atomicAdd(&g_hist[base + 1], 1.0f);                    \
    }
    EOP(s4.x, t4.x);
    EOP(s4.y, t4.y);
    EOP(s4.z, t4.z);
    EOP(s4.w, t4.w);
#undef EOP
}

// ---------------------------------------------------------------------------
// K5: per graph — suffix sums over buckets, reconstruct hg, then 3-layer head
__global__ __launch_bounds__(128) void k_final(const float* __restrict__ W1,
                                               const float* __restrict__ b1,
                                               const float* __restrict__ W2,
                                               const float* __restrict__ b2,
                                               const float* __restrict__ Wf1,
                                               const float* __restrict__ bf1,
                                               const float* __restrict__ Wf2,
                                               const float* __restrict__ bf2,
                                               float* __restrict__ out) {
    __shared__ float bs[NB], bc[NB];
    __shared__ float suffS[NB + 1], suffC[NB + 1];
    __shared__ float a_sh[ED], h_sh[ED];
    int g = blockIdx.x;
    int d = threadIdx.x;

    for (int idx = d; idx < NB; idx += ED) {
        bs[idx] = g_hist[(g * NB + idx) * 2];
        bc[idx] = g_hist[(g * NB + idx) * 2 + 1];
    }
    __syncthreads();
    if (d == 0) {
        float as = 0.f, ac = 0.f;
        suffS[NB] = 0.f; suffC[NB] = 0.f;
        for (int k = NB - 1; k >= 0; k--) {
            as += bs[k]; ac += bc[k];
            suffS[k] = as; suffC[k] = ac;
        }
    }
    __syncthreads();

    // hg[g,d] = (W1[d]*S_active + b1[d]*C_active) / count[g]
    {
        float w = W1[d], b = b1[d];
        int r = g_rank[d];
        float S = suffS[r + 1], C = suffC[r + 1];
        if (!g_side[d]) { S = suffS[0] - S; C = suffC[0] - C; }
        float invc = 1.0f / fmaxf((float)g_cnt[g], 1.0f);
        a_sh[d] = (w * S + b * C) * invc;
    }
    __syncthreads();

    // m1 = hg @ W2 + b2
    float acc = b2[d];
#pragma unroll 8
    for (int k = 0; k < ED; k++) acc = fmaf(a_sh[k], W2[k * ED + d], acc);
    h_sh[d] = acc;
    __syncthreads();

    // m2 = relu(m1 @ Wf1 + bf1)
    acc = bf1[d];
#pragma unroll 8
    for (int k = 0; k < ED; k++) acc = fmaf(h_sh[k], Wf1[k * ED + d], acc);
    acc = fmaxf(acc, 0.0f);
    __syncthreads();
    a_sh[d] = acc;
    __syncthreads();

    // out = m2 @ Wf2 + bf2
    if (d < NC) {
        float o = bf2[d];
#pragma unroll 8
        for (int k = 0; k < ED; k++) o = fmaf(a_sh[k], Wf2[k * NC + d], o);
        out[g * NC + d] = o;
    }
}

// ---------------------------------------------------------------------------
extern "C" void kernel_launch(void* const* d_in, const int* in_sizes, int n_in,
                              void* d_out, int out_size) {
    const float* feat = (const float*)d_in[0];
    const int*   src  = (const int*)d_in[1];
    const int*   dst  = (const int*)d_in[2];
    const int*   gids = (const int*)d_in[3];
    const float* W1   = (const float*)d_in[4];
    const float* b1   = (const float*)d_in[5];
    const float* W2   = (const float*)d_in[6];
    const float* b2   = (const float*)d_in[7];
    const float* Wf1  = (const float*)d_in[8];
    const float* bf1  = (const float*)d_in[9];
    const float* Wf2  = (const float*)d_in[10];
    const float* bf2  = (const float*)d_in[11];
    float* out = (float*)d_out;

    k_init<<<(N_NODES + 255) / 256, 256>>>(feat);
    k_prep<<<1, ED>>>(W1, b1);
    k_edges1<<<(N_EDGES / 4 + 255) / 256, 256>>>((const int4*)src, (const int4*)dst, feat);
    k_bucket<<<(N_NODES + 255) / 256, 256>>>(gids);
    k_edges2<<<(N_EDGES / 4 + 255) / 256, 256>>>((const int4*)src, (const int4*)dst, gids);
    k_final<<<NG, ED>>>(W1, b1, W2, b2, Wf1, bf1, Wf2, bf2, out);
}

// round 3
// speedup vs baseline: 1.8256x; 1.5859x over previous
#include <cuda_runtime.h>
#include <math_constants.h>

#define N_NODES 100000
#define N_EDGES 3200000
#define ED 128          // embed dim
#define NG 128          // num graphs
#define NC 10           // num classes
#define NB 129          // buckets = thresholds + 1

typedef unsigned long long u64;

// Scratch (device globals — no allocations allowed)
__device__ float g_s[N_NODES];               // s[n] = feat[n] + sum_in feat[src]
__device__ uint2 g_eb[N_NODES];              // per node: (encoded fixed-point s, bucket)
__device__ u64   g_hist[NG * NB];            // packed {sum<<24 | count} per (graph,bucket)
__device__ int   g_cnt[NG];                  // nodes per graph
__device__ float g_T[ED];                    // sorted thresholds
__device__ int   g_rank[ED];                 // sorted position of threshold d
__device__ int   g_side[ED];                 // 1: active = s > t (suffix); 0: prefix
__device__ int   g_bound[NG + 1];            // graph boundary table (gids sorted)

#define FP_SCALE 65536.0f
#define FP_BIAS  128.0f

// ---------------------------------------------------------------------------
// K0: fused setup.
//   all blocks: s = feat, zero hist/cnt
//   block 0:    thresholds + rank/side (needs intra-block sort-by-count)
//   block 1:    graph boundary table from sorted gids
__global__ void k_setup(const float* __restrict__ feat,
                        const float* __restrict__ W1, const float* __restrict__ b1,
                        const int* __restrict__ gids) {
    int tid = threadIdx.x;
    int i = blockIdx.x * blockDim.x + tid;
    if (i < N_NODES) g_s[i] = feat[i];
    if (i < NG * NB) g_hist[i] = 0ull;
    if (i < NG) g_cnt[i] = 0;

    if (blockIdx.x == 0) {
        __shared__ float ts[ED];
        if (tid < ED) {
            float w = W1[tid], b = b1[tid];
            float t; int side;
            if (w > 0.f)      { t = -b / w; side = 1; }
            else if (w < 0.f) { t = -b / w; side = 0; }
            else              { side = 1; t = (b > 0.f) ? -CUDART_INF_F : CUDART_INF_F; }
            ts[tid] = t;
            g_side[tid] = side;
        }
        __syncthreads();
        if (tid < ED) {
            float t = ts[tid];
            int r = 0;
#pragma unroll 8
            for (int j = 0; j < ED; j++) {
                float tj = ts[j];
                r += (tj < t) || (tj == t && j < tid);
            }
            g_rank[tid] = r;
            g_T[r] = t;
        }
    } else if (blockIdx.x == 1) {
        // boundary[g] = first node index with gids >= g
        if (tid <= NG) {
            int g = tid;
            int lo = 0, hi = N_NODES;
            while (lo < hi) {
                int mid = (lo + hi) >> 1;
                if (__ldg(&gids[mid]) < g) lo = mid + 1; else hi = mid;
            }
            g_bound[g] = lo;
        }
    }
}

// ---------------------------------------------------------------------------
// K1: edge pass 1 — s[dst] += feat[src]
__global__ void k_edges1(const int4* __restrict__ src4, const int4* __restrict__ dst4,
                         const float* __restrict__ feat) {
    int i = blockIdx.x * blockDim.x + threadIdx.x;
    if (i >= N_EDGES / 4) return;
    int4 s4 = src4[i];
    int4 t4 = dst4[i];
    float f0 = __ldg(&feat[s4.x]);
    float f1 = __ldg(&feat[s4.y]);
    float f2 = __ldg(&feat[s4.z]);
    float f3 = __ldg(&feat[s4.w]);
    atomicAdd(&g_s[t4.x], f0);
    atomicAdd(&g_s[t4.y], f1);
    atomicAdd(&g_s[t4.z], f2);
    atomicAdd(&g_s[t4.w], f3);
}

// ---------------------------------------------------------------------------
// K2: per node — bucket via binary search; encode fixed-point s; self term; counts
__global__ __launch_bounds__(256) void k_bucket(const int* __restrict__ gids) {
    __shared__ float T[ED];
    __shared__ int hcnt[NG];
    int tid = threadIdx.x;
    if (tid < ED) T[tid] = g_T[tid];
    if (tid < NG) hcnt[tid] = 0;
    __syncthreads();
    int n = blockIdx.x * 256 + tid;
    if (n < N_NODES) {
        float s = g_s[n];
        int b = 0;
#pragma unroll
        for (int st = 128; st > 0; st >>= 1) {
            int nb = b + st;
            if (nb <= ED && T[nb - 1] <= s) b = nb;
        }
        float sc = fminf(fmaxf(s, -FP_BIAS + 1.0f), FP_BIAS - 1.0f);
        unsigned int enc = (unsigned int)__float2int_rn((sc + FP_BIAS) * FP_SCALE);
        g_eb[n] = make_uint2(enc, (unsigned int)b);
        int g = gids[n];
        atomicAdd(&g_hist[g * NB + b], ((u64)enc << 24) | 1ull);
        atomicAdd(&hcnt[g], 1);
    }
    __syncthreads();
    if (tid < NG && hcnt[tid]) atomicAdd(&g_cnt[tid], hcnt[tid]);
}

// ---------------------------------------------------------------------------
// K3: edge pass 2 — hist[graph(dst)][bucket(src)] += packed(enc(src), 1)
//     graph(dst) via guided walk over the boundary table (gids sorted).
__global__ __launch_bounds__(256) void k_edges2(const int4* __restrict__ src4,
                                                const int4* __restrict__ dst4) {
    __shared__ int bnd[NG + 1];
    int tid = threadIdx.x;
    if (tid <= NG) bnd[tid] = g_bound[tid];
    __syncthreads();
    int i = blockIdx.x * blockDim.x + tid;
    if (i >= N_EDGES / 4) return;
    int4 s4 = src4[i];
    int4 t4 = dst4[i];
#define EOP(sn, tn) {                                                   \
        uint2 eb = __ldg(&g_eb[(sn)]);                                  \
        int t = (tn);                                                   \
        int g = (int)(((long long)t * NG) / N_NODES);                   \
        while (bnd[g + 1] <= t) g++;                                    \
        while (bnd[g] > t) g--;                                         \
        atomicAdd(&g_hist[g * NB + (int)eb.y], ((u64)eb.x << 24) | 1ull); \
    }
    EOP(s4.x, t4.x);
    EOP(s4.y, t4.y);
    EOP(s4.z, t4.z);
    EOP(s4.w, t4.w);
#undef EOP
}

// ---------------------------------------------------------------------------
// K4: per graph — decode hist, suffix sums, reconstruct hg, 3-layer head
__global__ __launch_bounds__(128) void k_final(const float* __restrict__ W1,
                                               const float* __restrict__ b1,
                                               const float* __restrict__ W2,
                                               const float* __restrict__ b2,
                                               const float* __restrict__ Wf1,
                                               const float* __restrict__ bf1,
                                               const float* __restrict__ Wf2,
                                               const float* __restrict__ bf2,
                                               float* __restrict__ out) {
    __shared__ float bs[NB], bc[NB];
    __shared__ float suffS[NB + 1], suffC[NB + 1];
    __shared__ float a_sh[ED], h_sh[ED];
    int g = blockIdx.x;
    int d = threadIdx.x;

    for (int idx = d; idx < NB; idx += ED) {
        u64 h = g_hist[g * NB + idx];
        long long cnt = (long long)(h & 0xFFFFFFull);
        long long sfix = (long long)(h >> 24) - cnt * (long long)(128 << 16);
        bs[idx] = (float)sfix * (1.0f / FP_SCALE);
        bc[idx] = (float)cnt;
    }
    __syncthreads();
    if (d == 0) {
        double as = 0.0, ac = 0.0;
        suffS[NB] = 0.f; suffC[NB] = 0.f;
        for (int k = NB - 1; k >= 0; k--) {
            as += (double)bs[k]; ac += (double)bc[k];
            suffS[k] = (float)as; suffC[k] = (float)ac;
        }
    }
    __syncthreads();

    // hg[g,d] = (W1[d]*S_active + b1[d]*C_active) / count[g]
    {
        float w = W1[d], b = b1[d];
        int r = g_rank[d];
        float S = suffS[r + 1], C = suffC[r + 1];
        if (!g_side[d]) { S = suffS[0] - S; C = suffC[0] - C; }
        float invc = 1.0f / fmaxf((float)g_cnt[g], 1.0f);
        a_sh[d] = (w * S + b * C) * invc;
    }
    __syncthreads();

    // m1 = hg @ W2 + b2
    float acc = b2[d];
#pragma unroll 8
    for (int k = 0; k < ED; k++) acc = fmaf(a_sh[k], W2[k * ED + d], acc);
    h_sh[d] = acc;
    __syncthreads();

    // m2 = relu(m1 @ Wf1 + bf1)
    acc = bf1[d];
#pragma unroll 8
    for (int k = 0; k < ED; k++) acc = fmaf(h_sh[k], Wf1[k * ED + d], acc);
    acc = fmaxf(acc, 0.0f);
    __syncthreads();
    a_sh[d] = acc;
    __syncthreads();

    // out = m2 @ Wf2 + bf2
    if (d < NC) {
        float o = bf2[d];
#pragma unroll 8
        for (int k = 0; k < ED; k++) o = fmaf(a_sh[k], Wf2[k * NC + d], o);
        out[g * NC + d] = o;
    }
}

// ---------------------------------------------------------------------------
extern "C" void kernel_launch(void* const* d_in, const int* in_sizes, int n_in,
                              void* d_out, int out_size) {
    const float* feat = (const float*)d_in[0];
    const int*   src  = (const int*)d_in[1];
    const int*   dst  = (const int*)d_in[2];
    const int*   gids = (const int*)d_in[3];
    const float* W1   = (const float*)d_in[4];
    const float* b1   = (const float*)d_in[5];
    const float* W2   = (const float*)d_in[6];
    const float* b2   = (const float*)d_in[7];
    const float* Wf1  = (const float*)d_in[8];
    const float* bf1  = (const float*)d_in[9];
    const float* Wf2  = (const float*)d_in[10];
    const float* bf2  = (const float*)d_in[11];
    float* out = (float*)d_out;

    k_setup<<<(N_NODES + 255) / 256, 256>>>(feat, W1, b1, gids);
    k_edges1<<<(N_EDGES / 4 + 255) / 256, 256>>>((const int4*)src, (const int4*)dst, feat);
    k_bucket<<<(N_NODES + 255) / 256, 256>>>(gids);
    k_edges2<<<(N_EDGES / 4 + 255) / 256, 256>>>((const int4*)src, (const int4*)dst);
    k_final<<<NG, ED>>>(W1, b1, W2, b2, Wf1, bf1, Wf2, bf2, out);
}